// round 3
// baseline (speedup 1.0000x reference)
#include <cuda_runtime.h>
#include <cuda_bf16.h>

// FeatureVectorInteractions: out[b] = < sum_i m0_i V0[b,i,:], sum_j m1_j V1[b,j,:] >
// B=4096, N=128, D=64.  Pure HBM-bound streaming reduction (268 MB of V reads).
//
// Structure: 1 warp per batch, 8 batches per 256-thread CTA, grid = B/8 = 512
// CTAs -> entire grid co-resident in one wave (512 <= 148*8). Warp-local
// shuffle reduction: no smem, no barriers in the reduction path. V0/V1 loaded
// with __ldcs (evict-first) since there is zero reuse.

#define NB 128                         // N
#define DV 64                          // D
#define F4_PER_ROW (DV / 4)            // 16 float4 per row
#define F4_PER_BATCH (NB * F4_PER_ROW) // 2048
#define BATCHES_PER_CTA 8

__global__ __launch_bounds__(256)
void fvi_kernel(const int* __restrict__ VI0,
                const int* __restrict__ VI1,
                const float4* __restrict__ V0,
                const float4* __restrict__ V1,
                float* __restrict__ out)
{
    const int tid  = threadIdx.x;
    const int w    = tid >> 5;          // warp id 0..7  -> local batch
    const int lane = tid & 31;
    const int b0   = blockIdx.x * BATCHES_PER_CTA;

    __shared__ float m0s[BATCHES_PER_CTA * NB];
    __shared__ float m1s[BATCHES_PER_CTA * NB];

    // ---- cooperative mask load: 8 batches * 128 ints each, int4 per thread ----
    {
        const int4* vi0 = (const int4*)(VI0 + b0 * NB);   // 256 int4
        const int4* vi1 = (const int4*)(VI1 + b0 * NB);
        int4 a = vi0[tid];
        int4 c = vi1[tid];
        float4* m0v = (float4*)m0s;
        float4* m1v = (float4*)m1s;
        m0v[tid] = make_float4(a.x > 0 ? 1.f : 0.f, a.y > 0 ? 1.f : 0.f,
                               a.z > 0 ? 1.f : 0.f, a.w > 0 ? 1.f : 0.f);
        m1v[tid] = make_float4(c.x > 0 ? 1.f : 0.f, c.y > 0 ? 1.f : 0.f,
                               c.z > 0 ? 1.f : 0.f, c.w > 0 ? 1.f : 0.f);
    }
    __syncthreads();

    // ---- per-warp streaming phase: warp w handles batch b0 + w ----
    const int b  = b0 + w;
    const int c  = lane & 15;           // float4 column 0..15
    const int rh = lane >> 4;           // row half 0..1

    const float4* v0 = V0 + (size_t)b * F4_PER_BATCH;
    const float4* v1 = V1 + (size_t)b * F4_PER_BATCH;
    const float*  m0 = m0s + w * NB;
    const float*  m1 = m1s + w * NB;

    float4 a0 = make_float4(0.f, 0.f, 0.f, 0.f);
    float4 a1 = make_float4(0.f, 0.f, 0.f, 0.f);

    #pragma unroll 8
    for (int k = 0; k < NB / 2; k++) {
        const int i = rh + 2 * k;       // row 0..127
        const float s0 = m0[i];
        const float s1 = m1[i];
        const float4 x = __ldcs(v0 + i * F4_PER_ROW + c);
        const float4 y = __ldcs(v1 + i * F4_PER_ROW + c);
        a0.x = fmaf(s0, x.x, a0.x);
        a0.y = fmaf(s0, x.y, a0.y);
        a0.z = fmaf(s0, x.z, a0.z);
        a0.w = fmaf(s0, x.w, a0.w);
        a1.x = fmaf(s1, y.x, a1.x);
        a1.y = fmaf(s1, y.y, a1.y);
        a1.z = fmaf(s1, y.z, a1.z);
        a1.w = fmaf(s1, y.w, a1.w);
    }

    // ---- warp-local reduction ----
    // combine the two row-halves (lane ^ 16): lanes now hold full u0[c], u1[c]
    a0.x += __shfl_xor_sync(0xffffffffu, a0.x, 16);
    a0.y += __shfl_xor_sync(0xffffffffu, a0.y, 16);
    a0.z += __shfl_xor_sync(0xffffffffu, a0.z, 16);
    a0.w += __shfl_xor_sync(0xffffffffu, a0.w, 16);
    a1.x += __shfl_xor_sync(0xffffffffu, a1.x, 16);
    a1.y += __shfl_xor_sync(0xffffffffu, a1.y, 16);
    a1.z += __shfl_xor_sync(0xffffffffu, a1.z, 16);
    a1.w += __shfl_xor_sync(0xffffffffu, a1.w, 16);

    // per-column dot (lanes l and l^16 hold identical values)
    float val = a0.x * a1.x + a0.y * a1.y + a0.z * a1.z + a0.w * a1.w;

    // reduce over the 16 columns
    #pragma unroll
    for (int o = 8; o > 0; o >>= 1)
        val += __shfl_xor_sync(0xffffffffu, val, o);

    if (lane == 0) out[b] = val;
}

extern "C" void kernel_launch(void* const* d_in, const int* in_sizes, int n_in,
                              void* d_out, int out_size)
{
    const int*    VI0 = (const int*)d_in[0];
    const int*    VI1 = (const int*)d_in[1];
    const float4* V0  = (const float4*)d_in[2];
    const float4* V1  = (const float4*)d_in[3];
    float*        out = (float*)d_out;

    const int B = in_sizes[0] / NB;            // 4096
    fvi_kernel<<<B / BATCHES_PER_CTA, 256>>>(VI0, VI1, V0, V1, out);
}